// round 2
// baseline (speedup 1.0000x reference)
#include <cuda_runtime.h>

#define NB 4
#define NK 128
#define NG 128

// ---- output layout (float32, tuple flattened & concatenated) ----
#define OFF_ROIS    0
#define OFF_OBJ     2048
#define OFF_DELTAS  526336
#define OFF_RANKS   528384
#define OFF_SPATIAL 528896

// One block per output slot (b, o). Each block independently recomputes the
// per-image assignment (cheap), finds its source proposal p, and writes:
//   - rois/deltas/ranks scalars for slot o (single thread)
//   - obj feature copy (256 x float4)
//   - analytic 32x32 spatial feature (no mask, no resize)
__global__ void __launch_bounds__(256) fused_kernel(
    const float* __restrict__ proposals,
    const float* __restrict__ obj_feat,
    const float* __restrict__ gt_boxes,
    const int*   __restrict__ gt_ranks,
    float*       __restrict__ out)
{
    __shared__ float4 s_prop[NK];
    __shared__ float4 s_gt[NG];
    __shared__ unsigned s_mask[4];   // pos bits, one word per warp of 32 proposals
    __shared__ int s_p;              // source proposal index for this slot
    __shared__ int4 s_box;           // integer spatial box

    const int bo = blockIdx.x;
    const int b  = bo >> 7;
    const int o  = bo & 127;
    const int t  = threadIdx.x;

    // cooperative load: threads 0..127 -> proposals, 128..255 -> gt boxes
    if (t < NK) {
        s_prop[t] = ((const float4*)proposals)[b * NK + t];
    } else {
        s_gt[t - NK] = ((const float4*)gt_boxes)[b * NG + (t - NK)];
    }
    __syncthreads();

    int   pos  = 0;
    int   bidx = 0;
    float py1 = 0.f, px1 = 0.f, py2 = 0.f, px2 = 0.f;

    if (t < NK) {
        const float4 pr = s_prop[t];
        py1 = pr.x; px1 = pr.y; py2 = pr.z; px2 = pr.w;
        const float ap = (py2 - py1) * (px2 - px1);

        float best = -1.0f;
        #pragma unroll 4
        for (int j = 0; j < NG; j++) {
            const float4 g = s_gt[j];
            const float iy1 = fmaxf(py1, g.x);
            const float ix1 = fmaxf(px1, g.y);
            const float iy2 = fminf(py2, g.z);
            const float ix2 = fminf(px2, g.w);
            const float inter = fmaxf(ix2 - ix1, 0.0f) * fmaxf(iy2 - iy1, 0.0f);
            const float ag = (g.z - g.x) * (g.w - g.y);
            const float iou = inter / (ap + ag - inter);
            if (iou > best) { best = iou; bidx = j; }   // first max wins
        }
        pos = (best >= 0.5f) ? 1 : 0;

        const unsigned m = __ballot_sync(0xFFFFFFFFu, pos);
        if ((t & 31) == 0) s_mask[t >> 5] = m;
    }
    __syncthreads();

    if (t < NK) {
        // stable partition rank via popcounts
        const unsigned m0 = s_mask[0], m1 = s_mask[1], m2 = s_mask[2], m3 = s_mask[3];
        const int npos = __popc(m0) + __popc(m1) + __popc(m2) + __popc(m3);
        const int w = t >> 5, l = t & 31;
        const unsigned below = (l == 0) ? 0u : (s_mask[w] & ((1u << l) - 1u));
        int rank_pos = __popc(below);
        if (w > 0) rank_pos += __popc(m0);
        if (w > 1) rank_pos += __popc(m1);
        if (w > 2) rank_pos += __popc(m2);
        const int dest = pos ? rank_pos : (npos + (t - rank_pos));

        if (dest == o) {
            s_p = t;

            // scalar outputs for slot o
            const int base = bo * 4;
            float* out_rois   = out + OFF_ROIS   + base;
            float* out_deltas = out + OFF_DELTAS + base;
            out_rois[0] = py1; out_rois[1] = px1;
            out_rois[2] = py2; out_rois[3] = px2;

            const float4 g = s_gt[bidx];
            float gy1 = g.x, gx1 = g.y, gy2 = g.z, gx2 = g.w;

            if (pos) {
                const float h  = py2 - py1, wd = px2 - px1;
                const float cy = py1 + 0.5f * h, cx = px1 + 0.5f * wd;
                const float gh = gy2 - gy1, gw = gx2 - gx1;
                const float gcy = gy1 + 0.5f * gh, gcx = gx1 + 0.5f * gw;
                out_deltas[0] = ((gcy - cy) / h)  / 0.1f;
                out_deltas[1] = ((gcx - cx) / wd) / 0.1f;
                out_deltas[2] = logf(gh / h)  / 0.2f;
                out_deltas[3] = logf(gw / wd) / 0.2f;
                out[OFF_RANKS + bo] = (float)gt_ranks[b * NG + bidx];
            } else {
                out_deltas[0] = 0.0f; out_deltas[1] = 0.0f;
                out_deltas[2] = 0.0f; out_deltas[3] = 0.0f;
                out[OFF_RANKS + bo] = 0.0f;
                gy1 = gx1 = gy2 = gx2 = 0.0f;   // roi_gt = 0 for negatives
            }

            // spatial box: window transform + denorm + round-half-even
            const float win0 = 128.0f / 1023.0f;
            const float win2 = 895.0f / 1023.0f;
            const float wsc  = win2 - win0;
            int by1 = (int)rintf(((gy1 - win0) / wsc) * 479.0f);
            int bx1 = (int)rintf(gx1 * 639.0f);
            int by2 = (int)rintf(((gy2 - win0) / wsc) * 479.0f + 1.0f);
            int bx2 = (int)rintf(gx2 * 639.0f + 1.0f);
            if (!((by2 - by1) * (bx2 - bx1) > 0)) { by1 = bx1 = by2 = bx2 = 0; }
            s_box = make_int4(by1, bx1, by2, bx2);
        }
    }
    __syncthreads();

    // obj permuted copy: 1024 floats = 256 float4
    const int p = s_p;
    const float4* src = (const float4*)(obj_feat + (size_t)(b * NK + p) * 1024);
    float4*       dst = (float4*)(out + OFF_OBJ + (size_t)bo * 1024);
    dst[t] = src[t];

    // analytic spatial feature: rows [4,28) carry the 24x32 resized mask,
    // value = 0.25*(fy(20i+9)+fy(20i+10))*(fx(20j+9)+fx(20j+10))
    const int4 bx = s_box;
    float* sp = out + OFF_SPATIAL + (size_t)bo * 1024;
    #pragma unroll
    for (int e = t; e < 1024; e += 256) {
        const int row = e >> 5;
        const int col = e & 31;
        float v = 0.0f;
        if (row >= 4 && row < 28) {
            const int r1 = 20 * (row - 4) + 9;
            const int r2 = r1 + 1;
            const int c1 = 20 * col + 9;
            const int c2 = c1 + 1;
            const float fy = (float)((bx.x < r1) && (r1 < bx.z))
                           + (float)((bx.x < r2) && (r2 < bx.z));
            const float fx = (float)((bx.y < c1) && (c1 < bx.w))
                           + (float)((bx.y < c2) && (c2 < bx.w));
            v = 0.25f * fy * fx;
        }
        sp[e] = v;
    }
}

extern "C" void kernel_launch(void* const* d_in, const int* in_sizes, int n_in,
                              void* d_out, int out_size)
{
    const float* proposals = (const float*)d_in[0];
    const float* obj_feat  = (const float*)d_in[1];
    const float* gt_boxes  = (const float*)d_in[2];
    const int*   gt_ranks  = (const int*)  d_in[3];
    float* out = (float*)d_out;

    fused_kernel<<<NB * NK, 256>>>(proposals, obj_feat, gt_boxes, gt_ranks, out);
}

// round 3
// speedup vs baseline: 3.3212x; 3.3212x over previous
#include <cuda_runtime.h>

#define NB 4
#define NK 128
#define NG 128

// ---- output layout (float32, tuple flattened & concatenated) ----
#define OFF_ROIS    0
#define OFF_OBJ     2048
#define OFF_DELTAS  526336
#define OFF_RANKS   528384
#define OFF_SPATIAL 528896

__device__ int  g_order[NB * NK];   // order[b*K+dest] = original proposal index
__device__ int4 g_box[NB * NK];     // integer spatial box per output slot

// grid = NB, block = 512. Thread t: segment seg = t>>7 scans GTs [32*seg, 32*seg+32)
// for proposal p = t&127. Partials merged in segment order (first-max preserved).
__global__ void __launch_bounds__(512) setup_kernel(
    const float* __restrict__ proposals,
    const float* __restrict__ gt_boxes,
    const int*   __restrict__ gt_ranks,
    float*       __restrict__ out)
{
    __shared__ float4 s_prop[NK];
    __shared__ float4 s_gt[NG];
    __shared__ float  s_best[4][NK];
    __shared__ int    s_bidx[4][NK];
    __shared__ unsigned s_mask[4];

    const int b = blockIdx.x;
    const int t = threadIdx.x;
    const int seg = t >> 7;
    const int p   = t & 127;

    if (t < NK)            s_prop[t]       = ((const float4*)proposals)[b * NK + t];
    else if (t < 2 * NK)   s_gt[t - NK]    = ((const float4*)gt_boxes)[b * NG + (t - NK)];
    __syncthreads();

    // partial argmax over 32 GTs (approximate div for comparison only)
    {
        const float4 pr = s_prop[p];
        const float ap = (pr.z - pr.x) * (pr.w - pr.y);
        float best = -1.0f;
        int   bidx = seg * 32;
        const int j0 = seg * 32;
        #pragma unroll 8
        for (int j = j0; j < j0 + 32; j++) {
            const float4 g = s_gt[j];
            const float iy1 = fmaxf(pr.x, g.x);
            const float ix1 = fmaxf(pr.y, g.y);
            const float iy2 = fminf(pr.z, g.z);
            const float ix2 = fminf(pr.w, g.w);
            const float inter = fmaxf(ix2 - ix1, 0.0f) * fmaxf(iy2 - iy1, 0.0f);
            const float ag = (g.z - g.x) * (g.w - g.y);
            const float iou = __fdividef(inter, ap + ag - inter);
            if (iou > best) { best = iou; bidx = j; }
        }
        s_best[seg][p] = best;
        s_bidx[seg][p] = bidx;
    }
    __syncthreads();

    if (t < NK) {
        // merge 4 segment partials in order (strict > keeps earliest max)
        float best = s_best[0][t];
        int   bidx = s_bidx[0][t];
        #pragma unroll
        for (int s = 1; s < 4; s++) {
            const float v = s_best[s][t];
            if (v > best) { best = v; bidx = s_bidx[s][t]; }
        }

        const float4 pr = s_prop[t];
        const float py1 = pr.x, px1 = pr.y, py2 = pr.z, px2 = pr.w;

        // exact IoU recompute for the winner (bit-matches reference threshold test)
        const float4 gb = s_gt[bidx];
        const float ap = (py2 - py1) * (px2 - px1);
        const float iy1 = fmaxf(py1, gb.x);
        const float ix1 = fmaxf(px1, gb.y);
        const float iy2 = fminf(py2, gb.z);
        const float ix2 = fminf(px2, gb.w);
        const float inter = fmaxf(ix2 - ix1, 0.0f) * fmaxf(iy2 - iy1, 0.0f);
        const float ag = (gb.z - gb.x) * (gb.w - gb.y);
        const float iou = inter / (ap + ag - inter);
        const int pos = (iou >= 0.5f) ? 1 : 0;

        const unsigned m = __ballot_sync(0xFFFFFFFFu, pos);
        if ((t & 31) == 0) s_mask[t >> 5] = m;
        __syncthreads();

        const unsigned m0 = s_mask[0], m1 = s_mask[1], m2 = s_mask[2], m3 = s_mask[3];
        const int npos = __popc(m0) + __popc(m1) + __popc(m2) + __popc(m3);
        const int w = t >> 5, l = t & 31;
        const unsigned below = (l == 0) ? 0u : (s_mask[w] & ((1u << l) - 1u));
        int rank_pos = __popc(below);
        if (w > 0) rank_pos += __popc(m0);
        if (w > 1) rank_pos += __popc(m1);
        if (w > 2) rank_pos += __popc(m2);
        const int dest = pos ? rank_pos : (npos + (t - rank_pos));

        const int bo = b * NK + dest;
        g_order[bo] = t;

        const int base = bo * 4;
        float* out_rois   = out + OFF_ROIS   + base;
        float* out_deltas = out + OFF_DELTAS + base;
        out_rois[0] = py1; out_rois[1] = px1;
        out_rois[2] = py2; out_rois[3] = px2;

        float gy1 = gb.x, gx1 = gb.y, gy2 = gb.z, gx2 = gb.w;
        if (pos) {
            const float h  = py2 - py1, wd = px2 - px1;
            const float cy = py1 + 0.5f * h, cx = px1 + 0.5f * wd;
            const float gh = gy2 - gy1, gw = gx2 - gx1;
            const float gcy = gy1 + 0.5f * gh, gcx = gx1 + 0.5f * gw;
            out_deltas[0] = ((gcy - cy) / h)  / 0.1f;
            out_deltas[1] = ((gcx - cx) / wd) / 0.1f;
            out_deltas[2] = logf(gh / h)  / 0.2f;
            out_deltas[3] = logf(gw / wd) / 0.2f;
            out[OFF_RANKS + bo] = (float)gt_ranks[b * NG + bidx];
        } else {
            out_deltas[0] = 0.0f; out_deltas[1] = 0.0f;
            out_deltas[2] = 0.0f; out_deltas[3] = 0.0f;
            out[OFF_RANKS + bo] = 0.0f;
            gy1 = gx1 = gy2 = gx2 = 0.0f;   // roi_gt = 0 for negatives
        }

        // integer spatial box: window transform + denorm + round-half-even
        const float win0 = 128.0f / 1023.0f;
        const float win2 = 895.0f / 1023.0f;
        const float wsc  = win2 - win0;
        int by1 = (int)rintf(((gy1 - win0) / wsc) * 479.0f);
        int bx1 = (int)rintf(gx1 * 639.0f);
        int by2 = (int)rintf(((gy2 - win0) / wsc) * 479.0f + 1.0f);
        int bx2 = (int)rintf(gx2 * 639.0f + 1.0f);
        if (!((by2 - by1) * (bx2 - bx1) > 0)) { by1 = bx1 = by2 = bx2 = 0; }
        g_box[bo] = make_int4(by1, bx1, by2, bx2);
    }
}

// grid = NB*NK, block = 256: permuted obj copy + analytic spatial paint.
__global__ void __launch_bounds__(256) scatter_kernel(
    const float* __restrict__ obj_feat,
    float*       __restrict__ out)
{
    const int bo = blockIdx.x;
    const int t  = threadIdx.x;
    const int b  = bo >> 7;
    const int p  = __ldg(&g_order[bo]);

    // obj permuted copy: 1024 floats = 256 float4
    const float4* src = (const float4*)(obj_feat + (size_t)(b * NK + p) * 1024);
    float4*       dst = (float4*)(out + OFF_OBJ + (size_t)bo * 1024);
    dst[t] = src[t];

    // analytic spatial feature: thread t writes elements [4t, 4t+4) as one float4.
    // rows [4,28) carry the 24x32 resized mask:
    //   value = 0.25*(fy(20i+9)+fy(20i+10))*(fx(20j+9)+fx(20j+10))
    const int4 bx = g_box[bo];
    const int row  = t >> 3;        // (4t)>>5
    const int col0 = (t & 7) * 4;   // (4t)&31

    float4 v = make_float4(0.f, 0.f, 0.f, 0.f);
    if (row >= 4 && row < 28) {
        const int r1 = 20 * (row - 4) + 9;
        const float fy = (float)((bx.x < r1)     && (r1     < bx.z))
                       + (float)((bx.x < r1 + 1) && (r1 + 1 < bx.z));
        const float s = 0.25f * fy;
        float* vv = &v.x;
        #pragma unroll
        for (int k = 0; k < 4; k++) {
            const int c1 = 20 * (col0 + k) + 9;
            const float fx = (float)((bx.y < c1)     && (c1     < bx.w))
                           + (float)((bx.y < c1 + 1) && (c1 + 1 < bx.w));
            vv[k] = s * fx;
        }
    }
    ((float4*)(out + OFF_SPATIAL + (size_t)bo * 1024))[t] = v;
}

extern "C" void kernel_launch(void* const* d_in, const int* in_sizes, int n_in,
                              void* d_out, int out_size)
{
    const float* proposals = (const float*)d_in[0];
    const float* obj_feat  = (const float*)d_in[1];
    const float* gt_boxes  = (const float*)d_in[2];
    const int*   gt_ranks  = (const int*)  d_in[3];
    float* out = (float*)d_out;

    setup_kernel<<<NB, 512>>>(proposals, gt_boxes, gt_ranks, out);
    scatter_kernel<<<NB * NK, 256>>>(obj_feat, out);
}